// round 8
// baseline (speedup 1.0000x reference)
#include <cuda_runtime.h>
#include <stdint.h>

#define N_NODES  50000
#define N_EDGES  800000
#define IN_F     128
#define OUT_F    128

#define SCAN_T   256
#define SCAN_B   ((N_NODES + SCAN_T - 1) / SCAN_T)   // 196

#define NUM_SM   148
#define TILE_M   128
#define N_TILES  ((N_NODES + TILE_M - 1) / TILE_M)   // 391

// -------------------- device scratch (no allocation allowed) ---------------
__device__ __align__(16) float g_agg[N_NODES * IN_F];  // normalized h rows
__device__ int   g_cnt[N_NODES];       // in-degree histogram
__device__ int   g_off[N_NODES];       // CSR row start
__device__ __align__(16) int g_rank[N_EDGES];  // within-node rank of each edge
__device__ int   g_srcs[N_EDGES];      // edge sources grouped by dst
__device__ int   g_bsums[SCAN_B];

// -------------------- 1) histogram + rank capture (4 edges/thread) ---------
__global__ void hist_kernel(const int* __restrict__ ei) {
    const int e4 = blockIdx.x * blockDim.x + threadIdx.x;
    if (e4 >= N_EDGES / 4) return;
    int4 d = reinterpret_cast<const int4*>(ei + N_EDGES)[e4];
    d.x = min(max(d.x, 0), N_NODES - 1);
    d.y = min(max(d.y, 0), N_NODES - 1);
    d.z = min(max(d.z, 0), N_NODES - 1);
    d.w = min(max(d.w, 0), N_NODES - 1);
    int4 r;
    r.x = atomicAdd(&g_cnt[d.x], 1);
    r.y = atomicAdd(&g_cnt[d.y], 1);
    r.z = atomicAdd(&g_cnt[d.z], 1);
    r.w = atomicAdd(&g_cnt[d.w], 1);
    reinterpret_cast<int4*>(g_rank)[e4] = r;   // contiguous store
}

// -------------------- 2) scanA: per-block sums -----------------------------
__global__ void scanA_kernel() {
    __shared__ int s[SCAN_T];
    const int gid = blockIdx.x * SCAN_T + threadIdx.x;
    s[threadIdx.x] = (gid < N_NODES) ? g_cnt[gid] : 0;
    __syncthreads();
    #pragma unroll
    for (int o = SCAN_T / 2; o > 0; o >>= 1) {
        if (threadIdx.x < o) s[threadIdx.x] += s[threadIdx.x + o];
        __syncthreads();
    }
    if (threadIdx.x == 0) g_bsums[blockIdx.x] = s[0];
}

// -------------------- 3) scanB: full exclusive scan ------------------------
__global__ void scanB_kernel() {
    __shared__ int sb[SCAN_T];
    __shared__ int st[SCAN_T];
    const int tid = threadIdx.x;

    int bv = (tid < SCAN_B) ? g_bsums[tid] : 0;
    sb[tid] = bv;
    __syncthreads();
    #pragma unroll
    for (int o = 1; o < SCAN_T; o <<= 1) {
        int t = (tid >= o) ? sb[tid - o] : 0;
        __syncthreads();
        sb[tid] += t;
        __syncthreads();
    }
    const int base = (blockIdx.x > 0) ? sb[blockIdx.x - 1] : 0;

    const int gid = blockIdx.x * SCAN_T + tid;
    int c = (gid < N_NODES) ? g_cnt[gid] : 0;
    st[tid] = c;
    __syncthreads();
    #pragma unroll
    for (int o = 1; o < SCAN_T; o <<= 1) {
        int t = (tid >= o) ? st[tid - o] : 0;
        __syncthreads();
        st[tid] += t;
        __syncthreads();
    }
    if (gid < N_NODES) g_off[gid] = base + st[tid] - c;
}

// -------------------- 4) bucket-fill: NO atomics (off + rank) --------------
__global__ void fill_kernel(const int* __restrict__ ei) {
    const int e4 = blockIdx.x * blockDim.x + threadIdx.x;
    if (e4 >= N_EDGES / 4) return;
    int4 s = reinterpret_cast<const int4*>(ei)[e4];
    int4 d = reinterpret_cast<const int4*>(ei + N_EDGES)[e4];
    int4 r = reinterpret_cast<const int4*>(g_rank)[e4];
    s.x = min(max(s.x, 0), N_NODES - 1);
    s.y = min(max(s.y, 0), N_NODES - 1);
    s.z = min(max(s.z, 0), N_NODES - 1);
    s.w = min(max(s.w, 0), N_NODES - 1);
    d.x = min(max(d.x, 0), N_NODES - 1);
    d.y = min(max(d.y, 0), N_NODES - 1);
    d.z = min(max(d.z, 0), N_NODES - 1);
    d.w = min(max(d.w, 0), N_NODES - 1);
    g_srcs[g_off[d.x] + r.x] = s.x;
    g_srcs[g_off[d.y] + r.y] = s.y;
    g_srcs[g_off[d.z] + r.z] = s.z;
    g_srcs[g_off[d.w] + r.w] = s.w;
}

// -------------------- 5) gather-aggregate: TWO warps per node --------------
// Block = 8 warps = 4 nodes. Each warp of a pair sums half the edge range
// (halves the serial load-latency rounds); odd warp dumps partials to smem,
// even warp combines, normalizes, stores.
__global__ void __launch_bounds__(256)
agg_kernel(const float4* __restrict__ x4) {
    __shared__ float4 part[4][32];

    const int warp = threadIdx.x >> 5;   // 0..7
    const int pair = warp >> 1;          // node slot 0..3
    const int half = warp & 1;
    const int lane = threadIdx.x & 31;
    const int node = blockIdx.x * 4 + pair;

    float4 r = make_float4(0.f, 0.f, 0.f, 0.f);
    int cnt = 0;

    if (node < N_NODES) {
        const int start = g_off[node];
        cnt = g_cnt[node];
        const int mid = start + (cnt >> 1);
        const int s0_ = half ? mid : start;
        const int e0_ = half ? (start + cnt) : mid;

        float4 a0 = make_float4(0.f, 0.f, 0.f, 0.f);
        float4 a1 = make_float4(0.f, 0.f, 0.f, 0.f);
        float4 a2 = make_float4(0.f, 0.f, 0.f, 0.f);
        float4 a3 = make_float4(0.f, 0.f, 0.f, 0.f);

        int e = s0_;
        for (; e + 7 < e0_; e += 8) {
            int i0 = g_srcs[e],     i1 = g_srcs[e + 1];
            int i2 = g_srcs[e + 2], i3 = g_srcs[e + 3];
            int i4 = g_srcs[e + 4], i5 = g_srcs[e + 5];
            int i6 = g_srcs[e + 6], i7 = g_srcs[e + 7];
            float4 v0 = __ldg(&x4[i0 * 32 + lane]);
            float4 v1 = __ldg(&x4[i1 * 32 + lane]);
            float4 v2 = __ldg(&x4[i2 * 32 + lane]);
            float4 v3 = __ldg(&x4[i3 * 32 + lane]);
            float4 v4 = __ldg(&x4[i4 * 32 + lane]);
            float4 v5 = __ldg(&x4[i5 * 32 + lane]);
            float4 v6 = __ldg(&x4[i6 * 32 + lane]);
            float4 v7 = __ldg(&x4[i7 * 32 + lane]);
            a0.x += v0.x; a0.y += v0.y; a0.z += v0.z; a0.w += v0.w;
            a1.x += v1.x; a1.y += v1.y; a1.z += v1.z; a1.w += v1.w;
            a2.x += v2.x; a2.y += v2.y; a2.z += v2.z; a2.w += v2.w;
            a3.x += v3.x; a3.y += v3.y; a3.z += v3.z; a3.w += v3.w;
            a0.x += v4.x; a0.y += v4.y; a0.z += v4.z; a0.w += v4.w;
            a1.x += v5.x; a1.y += v5.y; a1.z += v5.z; a1.w += v5.w;
            a2.x += v6.x; a2.y += v6.y; a2.z += v6.z; a2.w += v6.w;
            a3.x += v7.x; a3.y += v7.y; a3.z += v7.z; a3.w += v7.w;
        }
        // predicated tail: up to 7 edges, all loads issued together
        const int rem = e0_ - e;
        if (rem > 0) {
            int idx[7];
            #pragma unroll
            for (int i = 0; i < 7; i++)
                idx[i] = (i < rem) ? g_srcs[e + i] : 0;
            float4 v[7];
            #pragma unroll
            for (int i = 0; i < 7; i++)
                if (i < rem) v[i] = __ldg(&x4[idx[i] * 32 + lane]);
            #pragma unroll
            for (int i = 0; i < 7; i++)
                if (i < rem) {
                    float4* a = (i & 3) == 0 ? &a0 : (i & 3) == 1 ? &a1
                              : (i & 3) == 2 ? &a2 : &a3;
                    a->x += v[i].x; a->y += v[i].y; a->z += v[i].z; a->w += v[i].w;
                }
        }

        r.x = a0.x + a1.x + a2.x + a3.x;
        r.y = a0.y + a1.y + a2.y + a3.y;
        r.z = a0.z + a1.z + a2.z + a3.z;
        r.w = a0.w + a1.w + a2.w + a3.w;

        if (half) part[pair][lane] = r;
    }
    __syncthreads();
    if (node < N_NODES && !half) {
        const float4 p = part[pair][lane];
        const float inv = 1.0f / fmaxf((float)cnt, 1.0f);
        float4 o;
        o.x = (r.x + p.x) * inv;
        o.y = (r.y + p.y) * inv;
        o.z = (r.z + p.z) * inv;
        o.w = (r.w + p.w) * inv;
        reinterpret_cast<float4*>(g_agg)[(size_t)node * 32 + lane] = o;
    }
}

// -------------------- 6) persistent double-buffered GEMM -------------------
__device__ __forceinline__ void issue_h_tile(int tile, float* buf, int tid) {
    const int m0 = tile * TILE_M;
    const float4* aggbase = reinterpret_cast<const float4*>(g_agg);
    #pragma unroll
    for (int j = 0; j < 16; j++) {
        const int i = tid + j * 256;
        const int r = i >> 5;
        const int c = i & 31;
        const int m = min(m0 + r, N_NODES - 1);
        const float4* src = aggbase + (size_t)m * 32 + c;
        unsigned saddr = (unsigned)__cvta_generic_to_shared(buf + i * 4);
        asm volatile("cp.async.cg.shared.global [%0], [%1], 16;"
                     :: "r"(saddr), "l"(src));
    }
    asm volatile("cp.async.commit_group;");
}

__global__ void __launch_bounds__(256, 1)
gemm_kernel(float* __restrict__ out, const float* __restrict__ W,
            const float* __restrict__ b) {
    extern __shared__ float sm[];
    float* Wsm   = sm;
    float* Hbuf0 = sm + IN_F * OUT_F;
    float* Hbuf1 = Hbuf0 + TILE_M * IN_F;

    const int tid = threadIdx.x;

    int tile0 = blockIdx.x;
    if (tile0 < N_TILES) issue_h_tile(tile0, Hbuf0, tid);

    #pragma unroll 4
    for (int i = tid; i < OUT_F * IN_F; i += 256) {
        const int n = i >> 7;
        const int k = i & 127;
        Wsm[k * OUT_F + n] = W[i];
    }

    const int rowg = tid >> 4;
    const int colg = tid & 15;
    const int r0   = rowg * 8;
    const int n0   = colg * 8;

    float bb[8];
    #pragma unroll
    for (int j = 0; j < 8; j++) bb[j] = b[n0 + j];

    int it = 0;
    for (int tile = blockIdx.x; tile < N_TILES; tile += NUM_SM, it++) {
        float* cur = (it & 1) ? Hbuf1 : Hbuf0;
        float* nxt = (it & 1) ? Hbuf0 : Hbuf1;
        const int ntile = tile + NUM_SM;
        if (ntile < N_TILES) {
            issue_h_tile(ntile, nxt, tid);
            asm volatile("cp.async.wait_group 1;");
        } else {
            asm volatile("cp.async.wait_group 0;");
        }
        __syncthreads();

        const float4* Hsm4 = reinterpret_cast<const float4*>(cur);

        unsigned long long acc[8][4];
        #pragma unroll
        for (int i = 0; i < 8; i++)
            #pragma unroll
            for (int j = 0; j < 4; j++) acc[i][j] = 0ULL;

        for (int kk = 0; kk < IN_F; kk += 4) {
            float4 h4[8];
            #pragma unroll
            for (int i = 0; i < 8; i++)
                h4[i] = Hsm4[(r0 + i) * 32 + (kk >> 2)];

            #pragma unroll
            for (int j = 0; j < 4; j++) {
                const ulonglong2 wA = *reinterpret_cast<const ulonglong2*>(
                    &Wsm[(kk + j) * OUT_F + n0]);
                const ulonglong2 wB = *reinterpret_cast<const ulonglong2*>(
                    &Wsm[(kk + j) * OUT_F + n0 + 4]);
                #pragma unroll
                for (int i = 0; i < 8; i++) {
                    const float a = (j == 0) ? h4[i].x : (j == 1) ? h4[i].y
                                  : (j == 2) ? h4[i].z : h4[i].w;
                    unsigned long long aa;
                    asm("mov.b64 %0, {%1, %1};" : "=l"(aa) : "f"(a));
                    asm("fma.rn.f32x2 %0, %1, %2, %0;" : "+l"(acc[i][0]) : "l"(aa), "l"(wA.x));
                    asm("fma.rn.f32x2 %0, %1, %2, %0;" : "+l"(acc[i][1]) : "l"(aa), "l"(wA.y));
                    asm("fma.rn.f32x2 %0, %1, %2, %0;" : "+l"(acc[i][2]) : "l"(aa), "l"(wB.x));
                    asm("fma.rn.f32x2 %0, %1, %2, %0;" : "+l"(acc[i][3]) : "l"(aa), "l"(wB.y));
                }
            }
        }

        const int m0 = tile * TILE_M;
        #pragma unroll
        for (int i = 0; i < 8; i++) {
            const int m = m0 + r0 + i;
            if (m < N_NODES) {
                float lo, hi;
                float o[8];
                #pragma unroll
                for (int j = 0; j < 4; j++) {
                    asm("mov.b64 {%0, %1}, %2;" : "=f"(lo), "=f"(hi) : "l"(acc[i][j]));
                    o[2 * j]     = lo + bb[2 * j];
                    o[2 * j + 1] = hi + bb[2 * j + 1];
                }
                float4* orow = reinterpret_cast<float4*>(out + (size_t)m * OUT_F + n0);
                orow[0] = make_float4(o[0], o[1], o[2], o[3]);
                orow[1] = make_float4(o[4], o[5], o[6], o[7]);
            }
        }
        __syncthreads();
    }
}

// ---------------------------------------------------------------------------
extern "C" void kernel_launch(void* const* d_in, const int* in_sizes, int n_in,
                              void* d_out, int out_size) {
    const float* x  = nullptr;
    const int*   ei = nullptr;
    const float* W  = nullptr;
    const float* b  = nullptr;

    for (int i = 0; i < n_in; i++) {
        switch (in_sizes[i]) {
            case N_NODES * IN_F:  x  = (const float*)d_in[i]; break;
            case 2 * N_EDGES:     ei = (const int*)d_in[i];   break;
            case OUT_F * IN_F:    W  = (const float*)d_in[i]; break;
            case OUT_F:           b  = (const float*)d_in[i]; break;
            default: break;
        }
    }

    float* out = (float*)d_out;

    void* cnt_ptr = nullptr;
    cudaGetSymbolAddress(&cnt_ptr, g_cnt);
    cudaMemsetAsync(cnt_ptr, 0, N_NODES * sizeof(int));

    hist_kernel<<<(N_EDGES / 4 + 255) / 256, 256>>>(ei);
    scanA_kernel<<<SCAN_B, SCAN_T>>>();
    scanB_kernel<<<SCAN_B, SCAN_T>>>();
    fill_kernel<<<(N_EDGES / 4 + 255) / 256, 256>>>(ei);

    const int agg_blocks = (N_NODES + 3) / 4;    // 12500 (4 nodes/block)
    agg_kernel<<<agg_blocks, 256>>>(reinterpret_cast<const float4*>(x));

    const int smem_bytes = 3 * IN_F * OUT_F * (int)sizeof(float);  // 192KB
    cudaFuncSetAttribute(gemm_kernel, cudaFuncAttributeMaxDynamicSharedMemorySize,
                         smem_bytes);
    gemm_kernel<<<NUM_SM, 256, smem_bytes>>>(out, W, b);
}

// round 9
// speedup vs baseline: 1.1108x; 1.1108x over previous
#include <cuda_runtime.h>
#include <stdint.h>

#define N_NODES  50000
#define N_EDGES  800000
#define IN_F     128
#define OUT_F    128

#define SCAN_T   256
#define SCAN_B   ((N_NODES + SCAN_T - 1) / SCAN_T)   // 196

#define NUM_SM   148
#define TILE_M   128
#define N_TILES  ((N_NODES + TILE_M - 1) / TILE_M)   // 391

// -------------------- device scratch (no allocation allowed) ---------------
__device__ __align__(16) float g_agg[N_NODES * IN_F];  // normalized h rows
__device__ int   g_cnt4[4 * N_NODES];   // replicated histograms (stripe = edge%4)
__device__ int   g_base4[4 * N_NODES];  // per-(node,replica) output bases
__device__ int   g_cnt[N_NODES];        // per-node totals
__device__ int   g_off[N_NODES];        // CSR row start
__device__ __align__(16) int g_rank[N_EDGES];  // rank within (node,replica)
__device__ int   g_srcs[N_EDGES];       // edge sources grouped by dst
__device__ int   g_bsums[SCAN_B];

// -------------------- 1) histogram (replicated) + rank capture -------------
__global__ void hist_kernel(const int* __restrict__ ei) {
    const int e4 = blockIdx.x * blockDim.x + threadIdx.x;
    if (e4 >= N_EDGES / 4) return;
    int4 d = reinterpret_cast<const int4*>(ei + N_EDGES)[e4];
    d.x = min(max(d.x, 0), N_NODES - 1);
    d.y = min(max(d.y, 0), N_NODES - 1);
    d.z = min(max(d.z, 0), N_NODES - 1);
    d.w = min(max(d.w, 0), N_NODES - 1);
    // 4 replica arrays -> per-address contention / 4; return value = rank
    int4 r;
    r.x = atomicAdd(&g_cnt4[0 * N_NODES + d.x], 1);
    r.y = atomicAdd(&g_cnt4[1 * N_NODES + d.y], 1);
    r.z = atomicAdd(&g_cnt4[2 * N_NODES + d.z], 1);
    r.w = atomicAdd(&g_cnt4[3 * N_NODES + d.w], 1);
    reinterpret_cast<int4*>(g_rank)[e4] = r;   // contiguous store
}

// -------------------- 2) scanA: totals + per-block sums --------------------
__global__ void scanA_kernel() {
    __shared__ int s[SCAN_T];
    const int gid = blockIdx.x * SCAN_T + threadIdx.x;
    int tot = 0;
    if (gid < N_NODES) {
        tot = g_cnt4[gid] + g_cnt4[N_NODES + gid]
            + g_cnt4[2 * N_NODES + gid] + g_cnt4[3 * N_NODES + gid];
        g_cnt[gid] = tot;
    }
    s[threadIdx.x] = tot;
    __syncthreads();
    #pragma unroll
    for (int o = SCAN_T / 2; o > 0; o >>= 1) {
        if (threadIdx.x < o) s[threadIdx.x] += s[threadIdx.x + o];
        __syncthreads();
    }
    if (threadIdx.x == 0) g_bsums[blockIdx.x] = s[0];
}

// -------------------- 3) scanB: exclusive scan + replica bases -------------
__global__ void scanB_kernel() {
    __shared__ int sb[SCAN_T];
    __shared__ int st[SCAN_T];
    const int tid = threadIdx.x;

    int bv = (tid < SCAN_B) ? g_bsums[tid] : 0;
    sb[tid] = bv;
    __syncthreads();
    #pragma unroll
    for (int o = 1; o < SCAN_T; o <<= 1) {
        int t = (tid >= o) ? sb[tid - o] : 0;
        __syncthreads();
        sb[tid] += t;
        __syncthreads();
    }
    const int base = (blockIdx.x > 0) ? sb[blockIdx.x - 1] : 0;

    const int gid = blockIdx.x * SCAN_T + tid;
    int c = (gid < N_NODES) ? g_cnt[gid] : 0;
    st[tid] = c;
    __syncthreads();
    #pragma unroll
    for (int o = 1; o < SCAN_T; o <<= 1) {
        int t = (tid >= o) ? st[tid - o] : 0;
        __syncthreads();
        st[tid] += t;
        __syncthreads();
    }
    if (gid < N_NODES) {
        const int excl = base + st[tid] - c;
        const int c0 = g_cnt4[gid];
        const int c1 = g_cnt4[N_NODES + gid];
        const int c2 = g_cnt4[2 * N_NODES + gid];
        g_off[gid] = excl;
        g_base4[gid]               = excl;
        g_base4[N_NODES + gid]     = excl + c0;
        g_base4[2 * N_NODES + gid] = excl + c0 + c1;
        g_base4[3 * N_NODES + gid] = excl + c0 + c1 + c2;
    }
}

// -------------------- 4) bucket-fill: NO atomics (base + rank) -------------
__global__ void fill_kernel(const int* __restrict__ ei) {
    const int e4 = blockIdx.x * blockDim.x + threadIdx.x;
    if (e4 >= N_EDGES / 4) return;
    int4 s = reinterpret_cast<const int4*>(ei)[e4];
    int4 d = reinterpret_cast<const int4*>(ei + N_EDGES)[e4];
    int4 r = reinterpret_cast<const int4*>(g_rank)[e4];
    s.x = min(max(s.x, 0), N_NODES - 1);
    s.y = min(max(s.y, 0), N_NODES - 1);
    s.z = min(max(s.z, 0), N_NODES - 1);
    s.w = min(max(s.w, 0), N_NODES - 1);
    d.x = min(max(d.x, 0), N_NODES - 1);
    d.y = min(max(d.y, 0), N_NODES - 1);
    d.z = min(max(d.z, 0), N_NODES - 1);
    d.w = min(max(d.w, 0), N_NODES - 1);
    const int p0 = g_base4[0 * N_NODES + d.x] + r.x;
    const int p1 = g_base4[1 * N_NODES + d.y] + r.y;
    const int p2 = g_base4[2 * N_NODES + d.z] + r.z;
    const int p3 = g_base4[3 * N_NODES + d.w] + r.w;
    g_srcs[p0] = s.x;
    g_srcs[p1] = s.y;
    g_srcs[p2] = s.z;
    g_srcs[p3] = s.w;
}

// -------------------- 5) gather-aggregate: one warp per node (R7) ----------
__global__ void __launch_bounds__(256)
agg_kernel(const float4* __restrict__ x4) {
    const int node = (blockIdx.x * blockDim.x + threadIdx.x) >> 5;
    if (node >= N_NODES) return;
    const int lane = threadIdx.x & 31;

    const int start = g_off[node];
    const int cnt   = g_cnt[node];
    const int end   = start + cnt;

    float4 a0 = make_float4(0.f, 0.f, 0.f, 0.f);
    float4 a1 = make_float4(0.f, 0.f, 0.f, 0.f);
    float4 a2 = make_float4(0.f, 0.f, 0.f, 0.f);
    float4 a3 = make_float4(0.f, 0.f, 0.f, 0.f);

    int e = start;
    for (; e + 7 < end; e += 8) {
        int s0 = g_srcs[e],     s1 = g_srcs[e + 1];
        int s2 = g_srcs[e + 2], s3 = g_srcs[e + 3];
        int s4 = g_srcs[e + 4], s5 = g_srcs[e + 5];
        int s6 = g_srcs[e + 6], s7 = g_srcs[e + 7];
        float4 v0 = __ldg(&x4[s0 * 32 + lane]);
        float4 v1 = __ldg(&x4[s1 * 32 + lane]);
        float4 v2 = __ldg(&x4[s2 * 32 + lane]);
        float4 v3 = __ldg(&x4[s3 * 32 + lane]);
        float4 v4 = __ldg(&x4[s4 * 32 + lane]);
        float4 v5 = __ldg(&x4[s5 * 32 + lane]);
        float4 v6 = __ldg(&x4[s6 * 32 + lane]);
        float4 v7 = __ldg(&x4[s7 * 32 + lane]);
        a0.x += v0.x; a0.y += v0.y; a0.z += v0.z; a0.w += v0.w;
        a1.x += v1.x; a1.y += v1.y; a1.z += v1.z; a1.w += v1.w;
        a2.x += v2.x; a2.y += v2.y; a2.z += v2.z; a2.w += v2.w;
        a3.x += v3.x; a3.y += v3.y; a3.z += v3.z; a3.w += v3.w;
        a0.x += v4.x; a0.y += v4.y; a0.z += v4.z; a0.w += v4.w;
        a1.x += v5.x; a1.y += v5.y; a1.z += v5.z; a1.w += v5.w;
        a2.x += v6.x; a2.y += v6.y; a2.z += v6.z; a2.w += v6.w;
        a3.x += v7.x; a3.y += v7.y; a3.z += v7.z; a3.w += v7.w;
    }
    // predicated tail: up to 7 edges, all loads issue together (MLP=7)
    const int rem = end - e;
    if (rem > 0) {
        int idx[7];
        #pragma unroll
        for (int i = 0; i < 7; i++)
            idx[i] = (i < rem) ? g_srcs[e + i] : 0;
        float4 v[7];
        #pragma unroll
        for (int i = 0; i < 7; i++)
            if (i < rem) v[i] = __ldg(&x4[idx[i] * 32 + lane]);
        #pragma unroll
        for (int i = 0; i < 7; i++)
            if (i < rem) {
                float4* a = (i & 3) == 0 ? &a0 : (i & 3) == 1 ? &a1
                          : (i & 3) == 2 ? &a2 : &a3;
                a->x += v[i].x; a->y += v[i].y; a->z += v[i].z; a->w += v[i].w;
            }
    }

    const float inv = 1.0f / fmaxf((float)cnt, 1.0f);
    float4 r;
    r.x = (a0.x + a1.x + a2.x + a3.x) * inv;
    r.y = (a0.y + a1.y + a2.y + a3.y) * inv;
    r.z = (a0.z + a1.z + a2.z + a3.z) * inv;
    r.w = (a0.w + a1.w + a2.w + a3.w) * inv;
    reinterpret_cast<float4*>(g_agg)[(size_t)node * 32 + lane] = r;
}

// -------------------- 6) persistent double-buffered GEMM -------------------
__device__ __forceinline__ void issue_h_tile(int tile, float* buf, int tid) {
    const int m0 = tile * TILE_M;
    const float4* aggbase = reinterpret_cast<const float4*>(g_agg);
    #pragma unroll
    for (int j = 0; j < 16; j++) {
        const int i = tid + j * 256;
        const int r = i >> 5;
        const int c = i & 31;
        const int m = min(m0 + r, N_NODES - 1);
        const float4* src = aggbase + (size_t)m * 32 + c;
        unsigned saddr = (unsigned)__cvta_generic_to_shared(buf + i * 4);
        asm volatile("cp.async.cg.shared.global [%0], [%1], 16;"
                     :: "r"(saddr), "l"(src));
    }
    asm volatile("cp.async.commit_group;");
}

__global__ void __launch_bounds__(256, 1)
gemm_kernel(float* __restrict__ out, const float* __restrict__ W,
            const float* __restrict__ b) {
    extern __shared__ float sm[];
    float* Wsm   = sm;
    float* Hbuf0 = sm + IN_F * OUT_F;
    float* Hbuf1 = Hbuf0 + TILE_M * IN_F;

    const int tid = threadIdx.x;

    int tile0 = blockIdx.x;
    if (tile0 < N_TILES) issue_h_tile(tile0, Hbuf0, tid);

    #pragma unroll 4
    for (int i = tid; i < OUT_F * IN_F; i += 256) {
        const int n = i >> 7;
        const int k = i & 127;
        Wsm[k * OUT_F + n] = W[i];
    }

    const int rowg = tid >> 4;
    const int colg = tid & 15;
    const int r0   = rowg * 8;
    const int n0   = colg * 8;

    float bb[8];
    #pragma unroll
    for (int j = 0; j < 8; j++) bb[j] = b[n0 + j];

    int it = 0;
    for (int tile = blockIdx.x; tile < N_TILES; tile += NUM_SM, it++) {
        float* cur = (it & 1) ? Hbuf1 : Hbuf0;
        float* nxt = (it & 1) ? Hbuf0 : Hbuf1;
        const int ntile = tile + NUM_SM;
        if (ntile < N_TILES) {
            issue_h_tile(ntile, nxt, tid);
            asm volatile("cp.async.wait_group 1;");
        } else {
            asm volatile("cp.async.wait_group 0;");
        }
        __syncthreads();

        const float4* Hsm4 = reinterpret_cast<const float4*>(cur);

        unsigned long long acc[8][4];
        #pragma unroll
        for (int i = 0; i < 8; i++)
            #pragma unroll
            for (int j = 0; j < 4; j++) acc[i][j] = 0ULL;

        for (int kk = 0; kk < IN_F; kk += 4) {
            float4 h4[8];
            #pragma unroll
            for (int i = 0; i < 8; i++)
                h4[i] = Hsm4[(r0 + i) * 32 + (kk >> 2)];

            #pragma unroll
            for (int j = 0; j < 4; j++) {
                const ulonglong2 wA = *reinterpret_cast<const ulonglong2*>(
                    &Wsm[(kk + j) * OUT_F + n0]);
                const ulonglong2 wB = *reinterpret_cast<const ulonglong2*>(
                    &Wsm[(kk + j) * OUT_F + n0 + 4]);
                #pragma unroll
                for (int i = 0; i < 8; i++) {
                    const float a = (j == 0) ? h4[i].x : (j == 1) ? h4[i].y
                                  : (j == 2) ? h4[i].z : h4[i].w;
                    unsigned long long aa;
                    asm("mov.b64 %0, {%1, %1};" : "=l"(aa) : "f"(a));
                    asm("fma.rn.f32x2 %0, %1, %2, %0;" : "+l"(acc[i][0]) : "l"(aa), "l"(wA.x));
                    asm("fma.rn.f32x2 %0, %1, %2, %0;" : "+l"(acc[i][1]) : "l"(aa), "l"(wA.y));
                    asm("fma.rn.f32x2 %0, %1, %2, %0;" : "+l"(acc[i][2]) : "l"(aa), "l"(wB.x));
                    asm("fma.rn.f32x2 %0, %1, %2, %0;" : "+l"(acc[i][3]) : "l"(aa), "l"(wB.y));
                }
            }
        }

        const int m0 = tile * TILE_M;
        #pragma unroll
        for (int i = 0; i < 8; i++) {
            const int m = m0 + r0 + i;
            if (m < N_NODES) {
                float lo, hi;
                float o[8];
                #pragma unroll
                for (int j = 0; j < 4; j++) {
                    asm("mov.b64 {%0, %1}, %2;" : "=f"(lo), "=f"(hi) : "l"(acc[i][j]));
                    o[2 * j]     = lo + bb[2 * j];
                    o[2 * j + 1] = hi + bb[2 * j + 1];
                }
                float4* orow = reinterpret_cast<float4*>(out + (size_t)m * OUT_F + n0);
                orow[0] = make_float4(o[0], o[1], o[2], o[3]);
                orow[1] = make_float4(o[4], o[5], o[6], o[7]);
            }
        }
        __syncthreads();
    }
}

// ---------------------------------------------------------------------------
extern "C" void kernel_launch(void* const* d_in, const int* in_sizes, int n_in,
                              void* d_out, int out_size) {
    const float* x  = nullptr;
    const int*   ei = nullptr;
    const float* W  = nullptr;
    const float* b  = nullptr;

    for (int i = 0; i < n_in; i++) {
        switch (in_sizes[i]) {
            case N_NODES * IN_F:  x  = (const float*)d_in[i]; break;
            case 2 * N_EDGES:     ei = (const int*)d_in[i];   break;
            case OUT_F * IN_F:    W  = (const float*)d_in[i]; break;
            case OUT_F:           b  = (const float*)d_in[i]; break;
            default: break;
        }
    }

    float* out = (float*)d_out;

    void* cnt4_ptr = nullptr;
    cudaGetSymbolAddress(&cnt4_ptr, g_cnt4);
    cudaMemsetAsync(cnt4_ptr, 0, 4 * N_NODES * sizeof(int));

    hist_kernel<<<(N_EDGES / 4 + 255) / 256, 256>>>(ei);
    scanA_kernel<<<SCAN_B, SCAN_T>>>();
    scanB_kernel<<<SCAN_B, SCAN_T>>>();
    fill_kernel<<<(N_EDGES / 4 + 255) / 256, 256>>>(ei);

    const int agg_blocks = (N_NODES * 32 + 255) / 256;   // 6250
    agg_kernel<<<agg_blocks, 256>>>(reinterpret_cast<const float4*>(x));

    const int smem_bytes = 3 * IN_F * OUT_F * (int)sizeof(float);  // 192KB
    cudaFuncSetAttribute(gemm_kernel, cudaFuncAttributeMaxDynamicSharedMemorySize,
                         smem_bytes);
    gemm_kernel<<<NUM_SM, 256, smem_bytes>>>(out, W, b);
}